// round 2
// baseline (speedup 1.0000x reference)
#include <cuda_runtime.h>
#include <cstdint>

// FlowNet correlation on GB300/B200.
// out[b, dyi*21+dxi, h, w] = (1/256) * sum_c in1[b,c,h,w] * in2[b,c,h+dy,w+dx]
// dy = 2*(dyi-10), dx = 2*(dxi-10), zero padding outside [0,H)x[0,W).
//
// Shapes: B=8, C=256, H=96, W=128, G=21, D=441.
//
// Strategy:
//  - Parity trick: dx even => query col w only touches key cols of same parity.
//    Store B rows parity-packed in smem so each thread's 24-float key window is
//    contiguous -> LDS.128, conflict free.
//  - CTA(32,11): one (b,h), 11 dy rows (grid.x=2 halves of 21), all 128 w.
//    Thread owns 4 same-parity w positions x 21 dx -> acc[4][21] in regs.
//  - Channels chunked by 8; double-buffered smem; LDG->reg->STS pipeline with
//    a SINGLE __syncthreads per chunk (sts(other) precedes compute(cur)).

#define CB    8      // batch
#define CC_   256    // channels
#define HH    96
#define WW    128
#define GG    21
#define DD    441
#define CHK   8      // channels per smem chunk
#define NCHK  32     // 256/8
#define NROW  11     // dy rows per CTA
#define SW    84     // parity array width: cols -20..146 step 2 -> 84 entries
#define NTHR  352    // 32*11

// smem layout (floats):
//  Bs[buf][CHK][NROW][2 par][SW]   : per buf 8*11*2*84 = 14784
//  As[buf][CHK][2 par][64]         : per buf 8*2*64    = 1024
#define B_BUF_FLOATS 14784
#define A_BUF_FLOATS 1024
#define A_REGION_OFF (2 * B_BUF_FLOATS)          // 29568
#define SMEM_FLOATS  (2 * B_BUF_FLOATS + 2 * A_BUF_FLOATS)  // 31616
#define SMEM_BYTES   (SMEM_FLOATS * 4)           // 126464

__global__ __launch_bounds__(NTHR, 1)
void corr_kernel(const float* __restrict__ in1,
                 const float* __restrict__ in2,
                 float* __restrict__ out)
{
    extern __shared__ float sm[];

    const int tx = threadIdx.x;
    const int ty = threadIdx.y;                 // dy row within CTA (warp-uniform)
    const int tid = ty * 32 + tx;
    const int s  = blockIdx.x;                  // dy half: 0 -> dyi 0..10, 1 -> 11..21(21 idle)
    const int h  = blockIdx.y;
    const int b  = blockIdx.z;

    // ---- zero parity-halo regions of both buffers (cols outside [0,W)) ----
    // halo idx: 0..9 and 74..83 in each SW-array.  2 buf * 8 c * 11 row * 2 par * 20
    for (int i = tid; i < 2 * CHK * NROW * 2 * 20; i += NTHR) {
        int hseg = i % 20;
        int rest = i / 20;
        int par  = rest & 1;  rest >>= 1;
        int row  = rest % NROW; rest /= NROW;
        int ci   = rest % CHK;
        int buf  = rest / CHK;
        int idx  = (hseg < 10) ? hseg : (64 + hseg);   // 0..9 , 74..83
        sm[buf * B_BUF_FLOATS + ((ci * NROW + row) * 2 + par) * SW + idx] = 0.0f;
    }
    __syncthreads();

    const int par    = tx >> 4;        // 0 = even cols, 1 = odd cols
    const int xi     = tx & 15;
    const int dy_idx = s * NROW + ty;  // 0..21 (21 = idle)
    const bool active = (dy_idx < GG);
    const int base_w = 8 * xi + par;   // w positions: base_w + 2k, k=0..3

    float acc[4][GG];
#pragma unroll
    for (int k = 0; k < 4; ++k)
#pragma unroll
        for (int d = 0; d < GG; ++d) acc[k][d] = 0.0f;

    // per-thread load task decomposition (fixed across chunks):
    // B tasks: t = tid + 352*i, i=0..7 ; m=t&31, ci=(t>>5)&7, j=t>>8 (row 0..10)
    // A task : tid<256 ; m=tid&31, ci=tid>>5
    float4 rB[8];
    float4 rA = make_float4(0.f, 0.f, 0.f, 0.f);

    auto loadRegs = [&](int chunk) {
        const int c0 = chunk * CHK;
#pragma unroll
        for (int i = 0; i < 8; ++i) {
            const int t  = tid + NTHR * i;
            const int m  = t & 31;
            const int ci = (t >> 5) & 7;
            const int j  = t >> 8;
            const int r  = h + 2 * (s * NROW + j) - 20;
            if ((unsigned)r < (unsigned)HH) {
                rB[i] = *reinterpret_cast<const float4*>(
                    in2 + ((((long)b * CC_ + c0 + ci) * HH + r) * WW + 4 * m));
            } else {
                rB[i] = make_float4(0.f, 0.f, 0.f, 0.f);
            }
        }
        if (tid < 256) {
            const int m  = tid & 31;
            const int ci = tid >> 5;
            rA = *reinterpret_cast<const float4*>(
                in1 + ((((long)b * CC_ + c0 + ci) * HH + h) * WW + 4 * m));
        }
    };

    auto stsRegs = [&](int buf) {
        float* B = sm + buf * B_BUF_FLOATS;
#pragma unroll
        for (int i = 0; i < 8; ++i) {
            const int t  = tid + NTHR * i;
            const int m  = t & 31;
            const int ci = (t >> 5) & 7;
            const int j  = t >> 8;
            float* pe = B + ((ci * NROW + j) * 2 + 0) * SW + 2 * m + 10;
            float* po = B + ((ci * NROW + j) * 2 + 1) * SW + 2 * m + 10;
            *reinterpret_cast<float2*>(pe) = make_float2(rB[i].x, rB[i].z);
            *reinterpret_cast<float2*>(po) = make_float2(rB[i].y, rB[i].w);
        }
        if (tid < 256) {
            const int m  = tid & 31;
            const int ci = tid >> 5;
            float* A = sm + A_REGION_OFF + buf * A_BUF_FLOATS;
            float* pe = A + (ci * 2 + 0) * 64 + 2 * m;
            float* po = A + (ci * 2 + 1) * 64 + 2 * m;
            *reinterpret_cast<float2*>(pe) = make_float2(rA.x, rA.z);
            *reinterpret_cast<float2*>(po) = make_float2(rA.y, rA.w);
        }
    };

    auto computeBuf = [&](int buf) {
        const float* Bb = sm + buf * B_BUF_FLOATS;
        const float* Ab = sm + A_REGION_OFF + buf * A_BUF_FLOATS;
#pragma unroll
        for (int ci = 0; ci < CHK; ++ci) {
            const float4 q4 = *reinterpret_cast<const float4*>(
                Ab + (ci * 2 + par) * 64 + 4 * xi);
            const float qv[4] = {q4.x, q4.y, q4.z, q4.w};
            const float* Bp = Bb + ((ci * NROW + ty) * 2 + par) * SW + 4 * xi;
#pragma unroll
            for (int j4 = 0; j4 < 24; j4 += 4) {
                const float4 b4 = *reinterpret_cast<const float4*>(Bp + j4);
                const float bv[4] = {b4.x, b4.y, b4.z, b4.w};
#pragma unroll
                for (int jj = 0; jj < 4; ++jj) {
#pragma unroll
                    for (int kk = 0; kk < 4; ++kk) {
                        const int dxi = j4 + jj - kk;       // compile-time
                        if (dxi >= 0 && dxi < GG)
                            acc[kk][dxi] = fmaf(qv[kk], bv[jj], acc[kk][dxi]);
                    }
                }
            }
        }
    };

    // ---- software pipeline over 32 channel chunks, ONE sync per chunk ----
    // Invariant at top of iter k: buf (k&1) full+synced, other buf free.
    loadRegs(0);
    stsRegs(0);
    __syncthreads();

    for (int k = 0; k < NCHK; ++k) {
        const int cur = k & 1;
        if (k + 1 < NCHK) {
            loadRegs(k + 1);        // LDG chunk k+1
            stsRegs(1 - cur);       // fill free buffer (consumed at k-1, synced)
        }
        if (active) computeBuf(cur);
        __syncthreads();            // cur fully read; other fully written
    }

    // ---- write results ----
    if (active) {
        const float scale = 1.0f / 256.0f;
        const int obase = ((b * DD + dy_idx * GG) * HH + h) * WW + base_w;
#pragma unroll
        for (int dxi = 0; dxi < GG; ++dxi) {
#pragma unroll
            for (int kk = 0; kk < 4; ++kk) {
                out[obase + dxi * (HH * WW) + 2 * kk] = acc[kk][dxi] * scale;
            }
        }
    }
}

extern "C" void kernel_launch(void* const* d_in, const int* in_sizes, int n_in,
                              void* d_out, int out_size)
{
    const float* in1 = (const float*)d_in[0];
    const float* in2 = (const float*)d_in[1];
    float* out = (float*)d_out;

    (void)in_sizes; (void)n_in; (void)out_size;

    cudaFuncSetAttribute(corr_kernel,
                         cudaFuncAttributeMaxDynamicSharedMemorySize,
                         SMEM_BYTES);

    dim3 grid(2, HH, CB);
    dim3 block(32, NROW, 1);
    corr_kernel<<<grid, block, SMEM_BYTES>>>(in1, in2, out);
}

// round 3
// speedup vs baseline: 1.0088x; 1.0088x over previous
#include <cuda_runtime.h>
#include <cstdint>

// FlowNet correlation on GB300/B200 — R3: packed f32x2 FMA (FFMA2).
// out[b, dyi*21+dxi, h, w] = (1/256) * sum_c in1[b,c,h,w] * in2[b,c,h+dy,w+dx]
// dy = 2*(dyi-10), dx = 2*(dxi-10), zero padding.
// Shapes: B=8, C=256, H=96, W=128, G=21, D=441.
//
//  - Parity-packed smem rows -> contiguous 24-float key windows, LDS.128.
//  - CTA(32,11): one (b,h), 11 dy rows, all 128 w. Thread: 4 w x 21 dx.
//  - Accumulators paired along dxi with per-kk phase so every 64-bit B operand
//    is an even-aligned pair straight from the LDS.128 quad -> fma.rn.f32x2
//    halves FMA-pipe issue with no window repacking.

#define CB    8
#define CC_   256
#define HH    96
#define WW    128
#define GG    21
#define DD    441
#define CHK   8
#define NCHK  32
#define NROW  11
#define SW    84
#define NTHR  352

#define B_BUF_FLOATS 14784
#define A_BUF_FLOATS 1024
#define A_REGION_OFF (2 * B_BUF_FLOATS)
#define SMEM_FLOATS  (2 * B_BUF_FLOATS + 2 * A_BUF_FLOATS)
#define SMEM_BYTES   (SMEM_FLOATS * 4)           // 126464

__device__ __forceinline__ uint64_t pk2(float lo, float hi) {
    uint64_t r;
    asm("mov.b64 %0, {%1, %2};" : "=l"(r) : "f"(lo), "f"(hi));
    return r;
}
__device__ __forceinline__ void upk2(uint64_t v, float& lo, float& hi) {
    asm("mov.b64 {%0, %1}, %2;" : "=f"(lo), "=f"(hi) : "l"(v));
}
__device__ __forceinline__ void ffma2(uint64_t& c, uint64_t a, uint64_t b) {
    asm("fma.rn.f32x2 %0, %1, %2, %0;" : "+l"(c) : "l"(a), "l"(b));
}

__global__ __launch_bounds__(NTHR, 1)
void corr_kernel(const float* __restrict__ in1,
                 const float* __restrict__ in2,
                 float* __restrict__ out)
{
    extern __shared__ float sm[];

    const int tx = threadIdx.x;
    const int ty = threadIdx.y;
    const int tid = ty * 32 + tx;
    const int s  = blockIdx.x;                  // dy half
    const int h  = blockIdx.y;
    const int b  = blockIdx.z;

    // ---- zero parity-halo regions of both buffers ----
    for (int i = tid; i < 2 * CHK * NROW * 2 * 20; i += NTHR) {
        int hseg = i % 20;
        int rest = i / 20;
        int par  = rest & 1;  rest >>= 1;
        int row  = rest % NROW; rest /= NROW;
        int ci   = rest % CHK;
        int buf  = rest / CHK;
        int idx  = (hseg < 10) ? hseg : (64 + hseg);
        sm[buf * B_BUF_FLOATS + ((ci * NROW + row) * 2 + par) * SW + idx] = 0.0f;
    }
    __syncthreads();

    const int par    = tx >> 4;
    const int xi     = tx & 15;
    const int dy_idx = s * NROW + ty;
    const bool active = (dy_idx < GG);
    const int base_w = 8 * xi + par;

    // paired accumulators: accp[kk][p] covers dxi (2p,2p+1) for even kk,
    // (1+2p,2+2p) for odd kk. Scalar leftover: dxi=20 (kk even), dxi=0 (kk odd).
    uint64_t accp[4][10];
    float    accs[4];
#pragma unroll
    for (int kk = 0; kk < 4; ++kk) {
        accs[kk] = 0.0f;
#pragma unroll
        for (int p = 0; p < 10; ++p) accp[kk][p] = 0ull;
    }

    float4 rB[8];
    float4 rA = make_float4(0.f, 0.f, 0.f, 0.f);

    auto loadRegs = [&](int chunk) {
        const int c0 = chunk * CHK;
#pragma unroll
        for (int i = 0; i < 8; ++i) {
            const int t  = tid + NTHR * i;
            const int m  = t & 31;
            const int ci = (t >> 5) & 7;
            const int j  = t >> 8;
            const int r  = h + 2 * (s * NROW + j) - 20;
            if ((unsigned)r < (unsigned)HH) {
                rB[i] = *reinterpret_cast<const float4*>(
                    in2 + ((((long)b * CC_ + c0 + ci) * HH + r) * WW + 4 * m));
            } else {
                rB[i] = make_float4(0.f, 0.f, 0.f, 0.f);
            }
        }
        if (tid < 256) {
            const int m  = tid & 31;
            const int ci = tid >> 5;
            rA = *reinterpret_cast<const float4*>(
                in1 + ((((long)b * CC_ + c0 + ci) * HH + h) * WW + 4 * m));
        }
    };

    auto stsRegs = [&](int buf) {
        float* B = sm + buf * B_BUF_FLOATS;
#pragma unroll
        for (int i = 0; i < 8; ++i) {
            const int t  = tid + NTHR * i;
            const int m  = t & 31;
            const int ci = (t >> 5) & 7;
            const int j  = t >> 8;
            float* pe = B + ((ci * NROW + j) * 2 + 0) * SW + 2 * m + 10;
            float* po = B + ((ci * NROW + j) * 2 + 1) * SW + 2 * m + 10;
            *reinterpret_cast<float2*>(pe) = make_float2(rB[i].x, rB[i].z);
            *reinterpret_cast<float2*>(po) = make_float2(rB[i].y, rB[i].w);
        }
        if (tid < 256) {
            const int m  = tid & 31;
            const int ci = tid >> 5;
            float* A = sm + A_REGION_OFF + buf * A_BUF_FLOATS;
            float* pe = A + (ci * 2 + 0) * 64 + 2 * m;
            float* po = A + (ci * 2 + 1) * 64 + 2 * m;
            *reinterpret_cast<float2*>(pe) = make_float2(rA.x, rA.z);
            *reinterpret_cast<float2*>(po) = make_float2(rA.y, rA.w);
        }
    };

    auto computeBuf = [&](int buf) {
        const float* Bb = sm + buf * B_BUF_FLOATS;
        const float* Ab = sm + A_REGION_OFF + buf * A_BUF_FLOATS;
#pragma unroll
        for (int ci = 0; ci < CHK; ++ci) {
            const float4 q4 = *reinterpret_cast<const float4*>(
                Ab + (ci * 2 + par) * 64 + 4 * xi);
            uint64_t qp[4];
            qp[0] = pk2(q4.x, q4.x);
            qp[1] = pk2(q4.y, q4.y);
            qp[2] = pk2(q4.z, q4.z);
            qp[3] = pk2(q4.w, q4.w);
            const float qv[4] = {q4.x, q4.y, q4.z, q4.w};

            const float* Bp = Bb + ((ci * NROW + ty) * 2 + par) * SW + 4 * xi;
            float wf[24];
#pragma unroll
            for (int t = 0; t < 6; ++t) {
                const float4 w4 = *reinterpret_cast<const float4*>(Bp + 4 * t);
                wf[4 * t + 0] = w4.x; wf[4 * t + 1] = w4.y;
                wf[4 * t + 2] = w4.z; wf[4 * t + 3] = w4.w;
            }
            // even-aligned pairs (wf[2t], wf[2t+1]) — come from aligned quads
            uint64_t ep[12];
#pragma unroll
            for (int t = 0; t < 12; ++t) ep[t] = pk2(wf[2 * t], wf[2 * t + 1]);

            // kk=0: j0 = 2p      -> ep[p]
            // kk=1: j0 = 2p + 2  -> ep[p+1]
            // kk=2: j0 = 2p + 2  -> ep[p+1]
            // kk=3: j0 = 2p + 4  -> ep[p+2]
#pragma unroll
            for (int p = 0; p < 10; ++p) {
                ffma2(accp[0][p], qp[0], ep[p]);
                ffma2(accp[1][p], qp[1], ep[p + 1]);
                ffma2(accp[2][p], qp[2], ep[p + 1]);
                ffma2(accp[3][p], qp[3], ep[p + 2]);
            }
            // scalar leftovers: kk even -> dxi=20 (j=20+kk); kk odd -> dxi=0 (j=kk)
            accs[0] = fmaf(qv[0], wf[20], accs[0]);
            accs[2] = fmaf(qv[2], wf[22], accs[2]);
            accs[1] = fmaf(qv[1], wf[1],  accs[1]);
            accs[3] = fmaf(qv[3], wf[3],  accs[3]);
        }
    };

    // ---- software pipeline over 32 channel chunks, one sync per chunk ----
    loadRegs(0);
    stsRegs(0);
    __syncthreads();

    for (int k = 0; k < NCHK; ++k) {
        const int cur = k & 1;
        if (k + 1 < NCHK) {
            loadRegs(k + 1);
            stsRegs(1 - cur);
        }
        if (active) computeBuf(cur);
        __syncthreads();
    }

    // ---- write results ----
    if (active) {
        const float scale = 1.0f / 256.0f;
        const int obase = ((b * DD + dy_idx * GG) * HH + h) * WW + base_w;
#pragma unroll
        for (int kk = 0; kk < 4; ++kk) {
            const int dxi0 = (kk & 1) ? 1 : 0;        // first paired dxi
#pragma unroll
            for (int p = 0; p < 10; ++p) {
                float lo, hi;
                upk2(accp[kk][p], lo, hi);
                const int d0 = dxi0 + 2 * p;
                out[obase + d0 * (HH * WW) + 2 * kk]       = lo * scale;
                out[obase + (d0 + 1) * (HH * WW) + 2 * kk] = hi * scale;
            }
            const int ds = (kk & 1) ? 0 : 20;          // scalar leftover dxi
            out[obase + ds * (HH * WW) + 2 * kk] = accs[kk] * scale;
        }
    }
}

extern "C" void kernel_launch(void* const* d_in, const int* in_sizes, int n_in,
                              void* d_out, int out_size)
{
    const float* in1 = (const float*)d_in[0];
    const float* in2 = (const float*)d_in[1];
    float* out = (float*)d_out;

    (void)in_sizes; (void)n_in; (void)out_size;

    cudaFuncSetAttribute(corr_kernel,
                         cudaFuncAttributeMaxDynamicSharedMemorySize,
                         SMEM_BYTES);

    dim3 grid(2, HH, CB);
    dim3 block(32, NROW, 1);
    corr_kernel<<<grid, block, SMEM_BYTES>>>(in1, in2, out);
}